// round 5
// baseline (speedup 1.0000x reference)
#include <cuda_runtime.h>
#include <math.h>

// Problem constants
#define B_   2
#define S_   2048
#define D_   1024
#define H_   16
#define DK_  64
#define BS_  (B_ * S_)   // 4096

// ---------------------------------------------------------------------------
// Device scratch (no allocations allowed -> __device__ globals)
// ---------------------------------------------------------------------------
__device__ float g_Q[B_ * H_ * S_ * DK_];     // [B,H,S,DK]
__device__ float g_K[B_ * H_ * S_ * DK_];
__device__ float g_V[B_ * H_ * S_ * DK_];
__device__ float g_ctx[B_ * S_ * D_];         // [B,S,D] (== [B,S,H,DK])
__device__ float g_proj[B_ * S_ * D_];        // out-proj result before LN

// ---------------------------------------------------------------------------
// GEMM: Y[m][n] = sum_k A[m][k] * W[n][k] + bias[n]
//   A row-major [M x 1024], W row-major [1024 x 1024] (torch Linear weight)
//   MODE 0: store Y row-major [M x 1024]
//   MODE 1: store Y into [B,H,S,DK] layout (for Q/K/V)
// 128x128x8 tiles, 8x8 per thread, double-buffered smem. 256 threads.
// ---------------------------------------------------------------------------
template <int MODE>
__global__ __launch_bounds__(256, 2)
void gemm128(const float* __restrict__ A, const float* __restrict__ W,
             const float* __restrict__ bias, float* __restrict__ out)
{
    constexpr int K = D_;
    __shared__ float As[2][8][128];  // As[buf][k][m]
    __shared__ float Bs[2][8][128];  // Bs[buf][k][n]

    const int tid  = threadIdx.x;
    const int tx   = tid & 15;
    const int ty   = tid >> 4;
    const int row0 = blockIdx.y * 128;
    const int col0 = blockIdx.x * 128;

    const int lr = tid >> 1;         // 0..127 : tile row for loading
    const int lk = (tid & 1) << 2;   // 0 or 4 : k offset for loading

    const float* Aptr = A + (row0 + lr) * K + lk;
    const float* Wptr = W + (col0 + lr) * K + lk;

    float acc[8][8];
#pragma unroll
    for (int i = 0; i < 8; ++i)
#pragma unroll
        for (int j = 0; j < 8; ++j) acc[i][j] = 0.0f;

    // prologue: tile 0
    {
        float4 a4 = *(const float4*)Aptr;
        float4 b4 = *(const float4*)Wptr;
        As[0][lk + 0][lr] = a4.x; As[0][lk + 1][lr] = a4.y;
        As[0][lk + 2][lr] = a4.z; As[0][lk + 3][lr] = a4.w;
        Bs[0][lk + 0][lr] = b4.x; Bs[0][lk + 1][lr] = b4.y;
        Bs[0][lk + 2][lr] = b4.z; Bs[0][lk + 3][lr] = b4.w;
    }
    __syncthreads();

    constexpr int TILES = K / 8;   // 128
    for (int t = 0; t < TILES; ++t) {
        const int cur = t & 1;
        float4 na, nb;
        const bool has_next = (t + 1 < TILES);
        if (has_next) {
            na = *(const float4*)(Aptr + (t + 1) * 8);
            nb = *(const float4*)(Wptr + (t + 1) * 8);
        }
#pragma unroll
        for (int kk = 0; kk < 8; ++kk) {
            float a[8], b[8];
            *(float4*)(a)     = *(const float4*)&As[cur][kk][ty * 4];
            *(float4*)(a + 4) = *(const float4*)&As[cur][kk][64 + ty * 4];
            *(float4*)(b)     = *(const float4*)&Bs[cur][kk][tx * 4];
            *(float4*)(b + 4) = *(const float4*)&Bs[cur][kk][64 + tx * 4];
#pragma unroll
            for (int i = 0; i < 8; ++i)
#pragma unroll
                for (int j = 0; j < 8; ++j)
                    acc[i][j] += a[i] * b[j];
        }
        if (has_next) {
            const int nxt = cur ^ 1;
            As[nxt][lk + 0][lr] = na.x; As[nxt][lk + 1][lr] = na.y;
            As[nxt][lk + 2][lr] = na.z; As[nxt][lk + 3][lr] = na.w;
            Bs[nxt][lk + 0][lr] = nb.x; Bs[nxt][lk + 1][lr] = nb.y;
            Bs[nxt][lk + 2][lr] = nb.z; Bs[nxt][lk + 3][lr] = nb.w;
        }
        __syncthreads();
    }

    // epilogue: bias + store
    float bb[8];
    *(float4*)(bb)     = *(const float4*)&bias[col0 + tx * 4];
    *(float4*)(bb + 4) = *(const float4*)&bias[col0 + 64 + tx * 4];

#pragma unroll
    for (int ih = 0; ih < 2; ++ih) {
#pragma unroll
        for (int i = 0; i < 4; ++i) {
            const int m = row0 + ih * 64 + ty * 4 + i;
#pragma unroll
            for (int jh = 0; jh < 2; ++jh) {
                float4 v;
                v.x = acc[ih * 4 + i][jh * 4 + 0] + bb[jh * 4 + 0];
                v.y = acc[ih * 4 + i][jh * 4 + 1] + bb[jh * 4 + 1];
                v.z = acc[ih * 4 + i][jh * 4 + 2] + bb[jh * 4 + 2];
                v.w = acc[ih * 4 + i][jh * 4 + 3] + bb[jh * 4 + 3];
                const int c = col0 + jh * 64 + tx * 4;
                if (MODE == 0) {
                    *(float4*)&out[m * D_ + c] = v;
                } else {
                    const int b  = m >> 11;       // / S_
                    const int s  = m & (S_ - 1);
                    const int h  = c >> 6;        // / DK_
                    const int dk = c & 63;
                    *(float4*)&out[(((b * H_ + h) * S_) + s) * DK_ + dk] = v;
                }
            }
        }
    }
}

// ---------------------------------------------------------------------------
// Flash attention, fp32. One block = one 64-row Q tile of one (b,h).
//   scores = (Q K^T)/8 - cpen*complexity[b, k]  ; causal ; online softmax ;
//   ctx += P V. Output to g_ctx in [B,S,D] layout.
// 256 threads: thread (ty,tx) owns rows ty*4+i, cols tx*4+j (4x4).
// smem = Qst(d-major) + {Kst(d-major) | Ps(row-major)} + Vs = exactly 48 KB.
// ---------------------------------------------------------------------------
__global__ __launch_bounds__(256)
void attn64(const float* __restrict__ cplx, const float* __restrict__ cpen_p)
{
    __shared__ float Qst[64 * 64];   // Qst[d*64 + r]
    __shared__ float KP [64 * 64];   // Kst[d*64 + c]  then  Ps[r*64 + j]
    __shared__ float Vs [64 * 64];   // Vs[j*64 + d]

    const int tid = threadIdx.x;
    const int tx  = tid & 15;
    const int ty  = tid >> 4;
    const int qt  = (gridDim.x - 1) - blockIdx.x;   // heavy (long) tiles first
    const int bh  = blockIdx.y;
    const int b   = bh >> 4;   // / H_
    const int h   = bh & 15;
    const float cpen = __ldg(cpen_p);

    const float* Qg = g_Q + (size_t)bh * S_ * DK_;
    const float* Kg = g_K + (size_t)bh * S_ * DK_;
    const float* Vg = g_V + (size_t)bh * S_ * DK_;

    // ---- load Q tile transposed (coalesced global reads) ----
    {
        const int r  = tid >> 2;
        const int d0 = (tid & 3) << 4;
        const float* src = Qg + (qt * 64 + r) * DK_ + d0;
#pragma unroll
        for (int q = 0; q < 4; ++q) {
            float4 v = *(const float4*)(src + q * 4);
            Qst[(d0 + q * 4 + 0) * 64 + r] = v.x;
            Qst[(d0 + q * 4 + 1) * 64 + r] = v.y;
            Qst[(d0 + q * 4 + 2) * 64 + r] = v.z;
            Qst[(d0 + q * 4 + 3) * 64 + r] = v.w;
        }
    }

    float m_i[4], l_i[4], acc[4][4];
#pragma unroll
    for (int i = 0; i < 4; ++i) {
        m_i[i] = -1e30f; l_i[i] = 0.0f;
#pragma unroll
        for (int j = 0; j < 4; ++j) acc[i][j] = 0.0f;
    }

    const int nkt = qt + 1;
    for (int kt = 0; kt < nkt; ++kt) {
        __syncthreads();   // prior iter done with KP/Vs (and Q visible on iter 0)

        // ---- load K (transposed) and V tiles ----
        {
            const int r  = tid >> 2;
            const int d0 = (tid & 3) << 4;
            const float* ks = Kg + (kt * 64 + r) * DK_ + d0;
            const float* vs = Vg + (kt * 64 + r) * DK_ + d0;
#pragma unroll
            for (int q = 0; q < 4; ++q) {
                float4 kv = *(const float4*)(ks + q * 4);
                KP[(d0 + q * 4 + 0) * 64 + r] = kv.x;
                KP[(d0 + q * 4 + 1) * 64 + r] = kv.y;
                KP[(d0 + q * 4 + 2) * 64 + r] = kv.z;
                KP[(d0 + q * 4 + 3) * 64 + r] = kv.w;
                *(float4*)&Vs[r * 64 + d0 + q * 4] = *(const float4*)(vs + q * 4);
            }
        }
        __syncthreads();

        // ---- scores: S = Q K^T ----
        float s[4][4];
#pragma unroll
        for (int i = 0; i < 4; ++i)
#pragma unroll
            for (int j = 0; j < 4; ++j) s[i][j] = 0.0f;

#pragma unroll 4
        for (int d = 0; d < 64; ++d) {
            float4 aq = *(const float4*)&Qst[d * 64 + ty * 4];
            float4 bk = *(const float4*)&KP [d * 64 + tx * 4];
            float a[4] = {aq.x, aq.y, aq.z, aq.w};
            float bv[4] = {bk.x, bk.y, bk.z, bk.w};
#pragma unroll
            for (int i = 0; i < 4; ++i)
#pragma unroll
                for (int j = 0; j < 4; ++j)
                    s[i][j] += a[i] * bv[j];
        }

        // scale + complexity penalty + causal mask
        {
            float4 cv = *(const float4*)&cplx[b * S_ + kt * 64 + tx * 4];
            float pen[4] = {cpen * cv.x, cpen * cv.y, cpen * cv.z, cpen * cv.w};
#pragma unroll
            for (int i = 0; i < 4; ++i)
#pragma unroll
                for (int j = 0; j < 4; ++j)
                    s[i][j] = s[i][j] * 0.125f - pen[j];
            if (kt == qt) {
#pragma unroll
                for (int i = 0; i < 4; ++i)
#pragma unroll
                    for (int j = 0; j < 4; ++j)
                        if (tx * 4 + j > ty * 4 + i) s[i][j] = -1e9f;
            }
        }
        __syncthreads();   // everyone done reading KP as Kst

        // ---- online softmax + stage P into KP ----
#pragma unroll
        for (int i = 0; i < 4; ++i) {
            float mx = fmaxf(fmaxf(s[i][0], s[i][1]), fmaxf(s[i][2], s[i][3]));
#pragma unroll
            for (int off = 1; off < 16; off <<= 1)
                mx = fmaxf(mx, __shfl_xor_sync(0xffffffffu, mx, off, 16));
            const float nm = fmaxf(m_i[i], mx);
            const float alpha = __expf(m_i[i] - nm);
            m_i[i] = nm;
            float rs = 0.0f;
#pragma unroll
            for (int j = 0; j < 4; ++j) {
                s[i][j] = __expf(s[i][j] - nm);
                rs += s[i][j];
            }
#pragma unroll
            for (int off = 1; off < 16; off <<= 1)
                rs += __shfl_xor_sync(0xffffffffu, rs, off, 16);
            l_i[i] = l_i[i] * alpha + rs;
#pragma unroll
            for (int j = 0; j < 4; ++j) acc[i][j] *= alpha;
            *(float4*)&KP[(ty * 4 + i) * 64 + tx * 4] =
                make_float4(s[i][0], s[i][1], s[i][2], s[i][3]);
        }
        __syncthreads();   // P visible

        // ---- ctx += P V ----
#pragma unroll 4
        for (int j = 0; j < 64; ++j) {
            float4 bv = *(const float4*)&Vs[j * 64 + tx * 4];
#pragma unroll
            for (int i = 0; i < 4; ++i) {
                const float p = KP[(ty * 4 + i) * 64 + j];
                acc[i][0] += p * bv.x;
                acc[i][1] += p * bv.y;
                acc[i][2] += p * bv.z;
                acc[i][3] += p * bv.w;
            }
        }
    }

    // ---- epilogue ----
#pragma unroll
    for (int i = 0; i < 4; ++i) {
        const float inv = 1.0f / l_i[i];
        const int srow = qt * 64 + ty * 4 + i;
        float4 v = make_float4(acc[i][0] * inv, acc[i][1] * inv,
                               acc[i][2] * inv, acc[i][3] * inv);
        *(float4*)&g_ctx[((size_t)(b * S_ + srow)) * D_ + h * DK_ + tx * 4] = v;
    }
}

// ---------------------------------------------------------------------------
// LayerNorm over D=1024 with residual add: out = LN(g_proj + query)*g + b
// One block per row, 256 threads x 4 elements.
// ---------------------------------------------------------------------------
__global__ __launch_bounds__(256)
void ln_resid(const float* __restrict__ resid, const float* __restrict__ gamma,
              const float* __restrict__ beta, float* __restrict__ out)
{
    __shared__ float rs[8], rq[8];
    const int row = blockIdx.x;
    const int tid = threadIdx.x;

    const float* xr = g_proj + (size_t)row * D_;
    const float* rr = resid  + (size_t)row * D_;

    float4 a = *(const float4*)&xr[tid * 4];
    float4 r = *(const float4*)&rr[tid * 4];
    float x0 = a.x + r.x, x1 = a.y + r.y, x2 = a.z + r.z, x3 = a.w + r.w;

    float s  = x0 + x1 + x2 + x3;
    float sq = x0 * x0 + x1 * x1 + x2 * x2 + x3 * x3;
#pragma unroll
    for (int off = 16; off >= 1; off >>= 1) {
        s  += __shfl_xor_sync(0xffffffffu, s,  off);
        sq += __shfl_xor_sync(0xffffffffu, sq, off);
    }
    const int wid = tid >> 5;
    if ((tid & 31) == 0) { rs[wid] = s; rq[wid] = sq; }
    __syncthreads();
    float tot = 0.0f, totq = 0.0f;
#pragma unroll
    for (int w = 0; w < 8; ++w) { tot += rs[w]; totq += rq[w]; }

    const float mean = tot * (1.0f / D_);
    const float var  = totq * (1.0f / D_) - mean * mean;
    const float rstd = rsqrtf(var + 1e-5f);

    float4 g = *(const float4*)&gamma[tid * 4];
    float4 be = *(const float4*)&beta[tid * 4];
    float4 o;
    o.x = (x0 - mean) * rstd * g.x + be.x;
    o.y = (x1 - mean) * rstd * g.y + be.y;
    o.z = (x2 - mean) * rstd * g.z + be.z;
    o.w = (x3 - mean) * rstd * g.w + be.w;
    *(float4*)&out[(size_t)row * D_ + tid * 4] = o;
}

// ---------------------------------------------------------------------------
// kernel_launch
// ---------------------------------------------------------------------------
extern "C" void kernel_launch(void* const* d_in, const int* in_sizes, int n_in,
                              void* d_out, int out_size)
{
    (void)in_sizes; (void)n_in; (void)out_size;

    const float* query = (const float*)d_in[0];
    const float* key   = (const float*)d_in[1];
    const float* value = (const float*)d_in[2];
    const float* cplx  = (const float*)d_in[3];
    // d_in[4] = mask (bool tril) — deterministic, applied analytically
    const float* wq = (const float*)d_in[5];
    const float* bq = (const float*)d_in[6];
    const float* wk = (const float*)d_in[7];
    const float* bk = (const float*)d_in[8];
    const float* wv = (const float*)d_in[9];
    const float* bv = (const float*)d_in[10];
    const float* wo = (const float*)d_in[11];
    const float* bo = (const float*)d_in[12];
    const float* lng = (const float*)d_in[13];
    const float* lnb = (const float*)d_in[14];
    const float* cpen = (const float*)d_in[15];
    float* out = (float*)d_out;

    void *pQ, *pK, *pV, *pCtx, *pProj;
    cudaGetSymbolAddress(&pQ,   g_Q);
    cudaGetSymbolAddress(&pK,   g_K);
    cudaGetSymbolAddress(&pV,   g_V);
    cudaGetSymbolAddress(&pCtx, g_ctx);
    cudaGetSymbolAddress(&pProj, g_proj);

    dim3 gg(D_ / 128, BS_ / 128);   // (8, 32)

    // Q/K/V projections -> [B,H,S,DK]
    gemm128<1><<<gg, 256>>>(query, wq, bq, (float*)pQ);
    gemm128<1><<<gg, 256>>>(key,   wk, bk, (float*)pK);
    gemm128<1><<<gg, 256>>>(value, wv, bv, (float*)pV);

    // Flash attention -> g_ctx [B,S,D]
    dim3 ga(S_ / 64, B_ * H_);      // (32, 32)
    attn64<<<ga, 256>>>(cplx, cpen);

    // Output projection -> g_proj [B,S,D]
    gemm128<0><<<gg, 256>>>((const float*)pCtx, wo, bo, (float*)pProj);

    // Residual + LayerNorm -> d_out
    ln_resid<<<BS_, 256>>>(query, lng, lnb, out);
}